// round 9
// baseline (speedup 1.0000x reference)
#include <cuda_runtime.h>
#include <cstdint>

// Problem constants
#define BB 8
#define LL 4096
#define DD 768
#define NROWS (BB * LL)        // 32768
#define NB 888                 // 148 SMs x 6 co-resident blocks (forced by launch_bounds)
#define NT 192                 // 6 warps; 192 threads = 768/4 float4 columns exactly

// Phase 1: 16-row chunks
#define RPC1 16
#define NCH1 (NROWS / RPC1)    // 2048
#define CH_PER_B (LL / RPC1)   // 256
// Phase 2: 32 units = 8 batches x 4 column groups of 192
#define DG 4
#define DPG (DD / DG)          // 192
// Phase 3: groups of 6 rows (one per warp), descending
#define NGRP3 ((NROWS + 5) / 6)  // 5462

// Scratch (device globals). No cache hints anywhere (R2/R3/R8 all failed).
__device__ __align__(16) float g_part[NCH1 * DD];     // 6 MB partial colsums
__device__ __align__(16) float g_sum[BB * DD];        // full column sums
__device__ float g_sqpart[BB * DG];                   // per-unit sum of squares
__device__ unsigned g_arrive = 0;                     // epoch barrier (monotone)
__device__ unsigned g_ticket1 = 0;                    // phase-1 ticket
__device__ unsigned g_ticket2 = 0;                    // phase-3 ticket

// Epoch-based grid barrier: monotone counter, no reset needed across replays.
__device__ __forceinline__ void grid_barrier() {
    __syncthreads();
    if (threadIdx.x == 0) {
        __threadfence();
        unsigned old = atomicAdd(&g_arrive, 1u);
        unsigned target = (old / NB + 1u) * NB;
        while ((int)(*(volatile unsigned*)&g_arrive - target) < 0)
            __nanosleep(32);
    }
    __syncthreads();
}

__global__ __launch_bounds__(NT, 6) void fused_kernel(const float* __restrict__ x,
                                                      const float* __restrict__ alpha,
                                                      float* __restrict__ out) {
    __shared__ unsigned s_claim[2];
    const int tid = threadIdx.x;

    // g_ticket2 holds a stale value from the previous replay; reset before
    // barrier 1 (phase 3 only reads it after barrier 2).
    if (blockIdx.x == 0 && tid == 0) g_ticket2 = 0;

    // ---- Phase 1: partial column sums. Ticketed 16-row chunks, ascending. ----
    // Thread t owns float4 column t; 4 independent accumulators, 4-batched loads.
    // One __syncthreads per chunk (double-buffered claim).
    {
        int it = 0;
        for (;; it++) {
            if (tid == 0) s_claim[it & 1] = atomicAdd(&g_ticket1, 1u);
            __syncthreads();
            const unsigned c = s_claim[it & 1];
            if (c >= NCH1) break;

            const float4* xp = reinterpret_cast<const float4*>(x) +
                               (size_t)c * RPC1 * (DD / 4) + tid;
            float4 s0 = make_float4(0.f, 0.f, 0.f, 0.f);
            float4 s1 = make_float4(0.f, 0.f, 0.f, 0.f);
            float4 s2 = make_float4(0.f, 0.f, 0.f, 0.f);
            float4 s3 = make_float4(0.f, 0.f, 0.f, 0.f);
#pragma unroll
            for (int i = 0; i < RPC1; i += 4) {
                float4 v0 = xp[(size_t)(i + 0) * (DD / 4)];
                float4 v1 = xp[(size_t)(i + 1) * (DD / 4)];
                float4 v2 = xp[(size_t)(i + 2) * (DD / 4)];
                float4 v3 = xp[(size_t)(i + 3) * (DD / 4)];
                s0.x += v0.x; s0.y += v0.y; s0.z += v0.z; s0.w += v0.w;
                s1.x += v1.x; s1.y += v1.y; s1.z += v1.z; s1.w += v1.w;
                s2.x += v2.x; s2.y += v2.y; s2.z += v2.z; s2.w += v2.w;
                s3.x += v3.x; s3.y += v3.y; s3.z += v3.z; s3.w += v3.w;
            }
            float4 s = make_float4((s0.x + s1.x) + (s2.x + s3.x),
                                   (s0.y + s1.y) + (s2.y + s3.y),
                                   (s0.z + s1.z) + (s2.z + s3.z),
                                   (s0.w + s1.w) + (s2.w + s3.w));
            reinterpret_cast<float4*>(g_part)[(size_t)c * (DD / 4) + tid] = s;
        }
    }

    grid_barrier();
    if (blockIdx.x == 0 && tid == 0) g_ticket1 = 0;   // for next replay

    // ---- Phase 2: finish column sums + per-unit square sums (32 blocks). ----
    if (blockIdx.x < BB * DG) {
        const int b = blockIdx.x >> 2;
        const int g = blockIdx.x & 3;
        const int d = g * DPG + tid;

        const float* p = g_part + (size_t)b * CH_PER_B * DD + d;
        float a0 = 0.f, a1 = 0.f, a2 = 0.f, a3 = 0.f;
#pragma unroll 4
        for (int c = 0; c < CH_PER_B; c += 4) {
            a0 += p[(size_t)(c + 0) * DD];
            a1 += p[(size_t)(c + 1) * DD];
            a2 += p[(size_t)(c + 2) * DD];
            a3 += p[(size_t)(c + 3) * DD];
        }
        const float s = (a0 + a1) + (a2 + a3);
        g_sum[b * DD + d] = s;

        __shared__ float red[NT];
        red[tid] = s * s;
        __syncthreads();
        if (tid < 96) red[tid] += red[tid + 96];
        __syncthreads();
        if (tid < 48) red[tid] += red[tid + 48];
        __syncthreads();
        if (tid < 32) {
            float v = red[tid] + (tid < 16 ? red[tid + 32] : 0.f);
#pragma unroll
            for (int off = 16; off > 0; off >>= 1)
                v += __shfl_xor_sync(0xFFFFFFFFu, v, off);
            if (tid == 0) g_sqpart[b * DG + g] = v;
        }
    }

    grid_barrier();

    // ---- Phase 3: finalize. Ticketed groups of 6 consecutive rows, DESCENDING.
    // One row per warp; warps fully independent (sum_b + coef read from
    // global, L1/L2-hot). The coherent descending frontier over ~5300 rows is
    // what converted ~80 MB of the second x read into L2 hits in R6.
    {
        const int warp = tid >> 5;
        const int lane = tid & 31;
        const float4* gsum4 = reinterpret_cast<const float4*>(g_sum);
        const double denom = (double)DD * (double)DD
                           * (double)LL * (double)LL * (double)LL * (double)LL;
        int prevb = -1;
        float coef = 0.f;

        int it = 0;
        for (;; it++) {
            if (tid == 0) s_claim[it & 1] = atomicAdd(&g_ticket2, 1u);
            __syncthreads();
            const unsigned cl = s_claim[it & 1];
            if (cl >= NGRP3) break;

            const int row = NROWS - 1 - ((int)cl * 6 + warp);   // descending
            if (row < 0) continue;
            const int b = row >> 12;
            const int l = row & (LL - 1);

            if (b != prevb) {
                float sq = g_sqpart[b * DG + 0] + g_sqpart[b * DG + 1]
                         + g_sqpart[b * DG + 2] + g_sqpart[b * DG + 3];
                coef = (float)((double)sq / denom);
                prevb = b;
            }

            const float4* xp = reinterpret_cast<const float4*>(x + (size_t)row * DD);
            const float4* mp = gsum4 + b * (DD / 4);
            float4 v[6];
            float dot = 0.f;
#pragma unroll
            for (int i = 0; i < 6; i++) {
                v[i] = xp[lane + i * 32];
                float4 m = mp[lane + i * 32];
                dot += v[i].x * m.x + v[i].y * m.y + v[i].z * m.z + v[i].w * m.w;
            }
#pragma unroll
            for (int off = 16; off > 0; off >>= 1)
                dot += __shfl_xor_sync(0xFFFFFFFFu, dot, off);

            const float y2 = dot * coef;
            const float a  = alpha[l];

            float4* op = reinterpret_cast<float4*>(out + (size_t)row * DD);
#pragma unroll
            for (int i = 0; i < 6; i++) {
                float4 o;
                o.x = a + y2 * v[i].x;
                o.y = a + y2 * v[i].y;
                o.z = a + y2 * v[i].z;
                o.w = a + y2 * v[i].w;
                op[lane + i * 32] = o;
            }
        }
    }
}

extern "C" void kernel_launch(void* const* d_in, const int* in_sizes, int n_in,
                              void* d_out, int out_size) {
    const float* x     = (const float*)d_in[0];   // [8, 4096, 768] f32
    const float* alpha = (const float*)d_in[1];   // [4096, 1] f32
    float* out = (float*)d_out;                   // [8, 4096, 768] f32

    fused_kernel<<<NB, NT>>>(x, alpha, out);
}

// round 10
// speedup vs baseline: 1.0407x; 1.0407x over previous
#include <cuda_runtime.h>
#include <cstdint>

// Problem constants
#define BB 8
#define LL 4096
#define DD 768
#define NROWS (BB * LL)        // 32768
#define NB 888                 // 148 SMs x 6 co-resident blocks
#define NT 192                 // 6 warps; 192 threads = 768/4 float4 columns exactly

// Phase 1: 16-row chunks, static interleaved ascending
#define RPC1 16
#define NCH1 (NROWS / RPC1)    // 2048
#define CH_PER_B (LL / RPC1)   // 256
// Phase 2: 32 units = 8 batches x 4 column groups of 192
#define DG 4
#define DPG (DD / DG)          // 192
// Phase 3: groups of 6 rows (one per warp), static interleaved descending
#define NGRP3 ((NROWS + 5) / 6)  // 5462

// Scratch (device globals). No cache hints anywhere (R2/R3/R8 all failed).
__device__ __align__(16) float g_part[NCH1 * DD];     // 6 MB partial colsums
__device__ __align__(16) float g_sum[BB * DD];        // full column sums
__device__ float g_sqpart[BB * DG];                   // per-unit sum of squares
__device__ unsigned g_arrive = 0;                     // epoch barrier (monotone)

// Epoch-based grid barrier: monotone counter, no reset needed across replays.
__device__ __forceinline__ void grid_barrier() {
    __syncthreads();
    if (threadIdx.x == 0) {
        __threadfence();
        unsigned old = atomicAdd(&g_arrive, 1u);
        unsigned target = (old / NB + 1u) * NB;
        while ((int)(*(volatile unsigned*)&g_arrive - target) < 0)
            __nanosleep(32);
    }
    __syncthreads();
}

__global__ __launch_bounds__(NT, 6) void fused_kernel(const float* __restrict__ x,
                                                      const float* __restrict__ alpha,
                                                      float* __restrict__ out) {
    const int tid = threadIdx.x;
    const int bid = blockIdx.x;

    // ---- Phase 1: partial column sums. Static chunks c = j*NB + bid (ascending).
    // All blocks sweep the same ascending band -> tail of x is L2-hot when
    // phase 3 starts there. Thread t owns float4 column t; no syncs, no atomics.
    for (int c = bid; c < NCH1; c += NB) {
        const float4* xp = reinterpret_cast<const float4*>(x) +
                           (size_t)c * RPC1 * (DD / 4) + tid;
        float4 s0 = make_float4(0.f, 0.f, 0.f, 0.f);
        float4 s1 = make_float4(0.f, 0.f, 0.f, 0.f);
        float4 s2 = make_float4(0.f, 0.f, 0.f, 0.f);
        float4 s3 = make_float4(0.f, 0.f, 0.f, 0.f);
#pragma unroll
        for (int i = 0; i < RPC1; i += 4) {
            float4 v0 = xp[(size_t)(i + 0) * (DD / 4)];
            float4 v1 = xp[(size_t)(i + 1) * (DD / 4)];
            float4 v2 = xp[(size_t)(i + 2) * (DD / 4)];
            float4 v3 = xp[(size_t)(i + 3) * (DD / 4)];
            s0.x += v0.x; s0.y += v0.y; s0.z += v0.z; s0.w += v0.w;
            s1.x += v1.x; s1.y += v1.y; s1.z += v1.z; s1.w += v1.w;
            s2.x += v2.x; s2.y += v2.y; s2.z += v2.z; s2.w += v2.w;
            s3.x += v3.x; s3.y += v3.y; s3.z += v3.z; s3.w += v3.w;
        }
        float4 s = make_float4((s0.x + s1.x) + (s2.x + s3.x),
                               (s0.y + s1.y) + (s2.y + s3.y),
                               (s0.z + s1.z) + (s2.z + s3.z),
                               (s0.w + s1.w) + (s2.w + s3.w));
        reinterpret_cast<float4*>(g_part)[(size_t)c * (DD / 4) + tid] = s;
    }

    grid_barrier();

    // ---- Phase 2: finish column sums + per-unit square sums (32 blocks). ----
    if (bid < BB * DG) {
        const int b = bid >> 2;
        const int g = bid & 3;
        const int d = g * DPG + tid;

        const float* p = g_part + (size_t)b * CH_PER_B * DD + d;
        float a0 = 0.f, a1 = 0.f, a2 = 0.f, a3 = 0.f;
#pragma unroll 4
        for (int c = 0; c < CH_PER_B; c += 4) {
            a0 += p[(size_t)(c + 0) * DD];
            a1 += p[(size_t)(c + 1) * DD];
            a2 += p[(size_t)(c + 2) * DD];
            a3 += p[(size_t)(c + 3) * DD];
        }
        const float s = (a0 + a1) + (a2 + a3);
        g_sum[b * DD + d] = s;

        __shared__ float red[NT];
        red[tid] = s * s;
        __syncthreads();
        if (tid < 96) red[tid] += red[tid + 96];
        __syncthreads();
        if (tid < 48) red[tid] += red[tid + 48];
        __syncthreads();
        if (tid < 32) {
            float v = red[tid] + (tid < 16 ? red[tid + 32] : 0.f);
#pragma unroll
            for (int off = 16; off > 0; off >>= 1)
                v += __shfl_xor_sync(0xFFFFFFFFu, v, off);
            if (tid == 0) g_sqpart[b * DG + g] = v;
        }
    }

    grid_barrier();

    // ---- Phase 3: finalize. Static groups g = j*NB + bid mapped to DESCENDING
    // rows; one row per warp, warps fully independent (no syncs in the loop).
    // All blocks at step j occupy the same ~5300-row descending band — the
    // coherent frontier that saves ~75 MB of the second x read (R6/R9 data).
    {
        const int warp = tid >> 5;
        const int lane = tid & 31;
        const float4* gsum4 = reinterpret_cast<const float4*>(g_sum);
        const double denom = (double)DD * (double)DD
                           * (double)LL * (double)LL * (double)LL * (double)LL;
        int prevb = -1;
        float coef = 0.f;

        for (int g = bid; g < NGRP3; g += NB) {
            const int row = NROWS - 1 - (g * 6 + warp);   // descending
            if (row < 0) continue;
            const int b = row >> 12;
            const int l = row & (LL - 1);

            if (b != prevb) {
                float sq = g_sqpart[b * DG + 0] + g_sqpart[b * DG + 1]
                         + g_sqpart[b * DG + 2] + g_sqpart[b * DG + 3];
                coef = (float)((double)sq / denom);
                prevb = b;
            }

            const float4* xp = reinterpret_cast<const float4*>(x + (size_t)row * DD);
            const float4* mp = gsum4 + b * (DD / 4);
            float4 v[6];
            float dot = 0.f;
#pragma unroll
            for (int i = 0; i < 6; i++) {
                v[i] = xp[lane + i * 32];
                float4 m = mp[lane + i * 32];
                dot += v[i].x * m.x + v[i].y * m.y + v[i].z * m.z + v[i].w * m.w;
            }
#pragma unroll
            for (int off = 16; off > 0; off >>= 1)
                dot += __shfl_xor_sync(0xFFFFFFFFu, dot, off);

            const float y2 = dot * coef;
            const float a  = alpha[l];

            float4* op = reinterpret_cast<float4*>(out + (size_t)row * DD);
#pragma unroll
            for (int i = 0; i < 6; i++) {
                float4 o;
                o.x = a + y2 * v[i].x;
                o.y = a + y2 * v[i].y;
                o.z = a + y2 * v[i].z;
                o.w = a + y2 * v[i].w;
                op[lane + i * 32] = o;
            }
        }
    }
}

extern "C" void kernel_launch(void* const* d_in, const int* in_sizes, int n_in,
                              void* d_out, int out_size) {
    const float* x     = (const float*)d_in[0];   // [8, 4096, 768] f32
    const float* alpha = (const float*)d_in[1];   // [4096, 1] f32
    float* out = (float*)d_out;                   // [8, 4096, 768] f32

    fused_kernel<<<NB, NT>>>(x, alpha, out);
}

// round 11
// speedup vs baseline: 1.1013x; 1.0583x over previous
#include <cuda_runtime.h>
#include <cstdint>

// Problem constants
#define BB 8
#define LL 4096
#define DD 768
#define NROWS (BB * LL)        // 32768
#define NB 512                 // blocks (<= 148*4 co-resident at 256 thr / <=64 regs)
#define NT 256                 // 8 warps
#define NWARPS (NB * 8)        // 4096 warps: 8 rows each in phase 1, 8 rows each in phase 3
#define RPW 8                  // rows per warp (phase 1)

// Scratch (device globals). No cache hints (R2/R3/R8 all failed).
__device__ __align__(16) float g_part[NB * DD];    // per-block column partials (1.5 MB)
__device__ __align__(16) float g_sum[BB * DD];     // full column sums
__device__ float g_sqpart[BB * 3];                 // per-colgroup sum of squares
__device__ unsigned g_arrive = 0;                  // epoch barrier (monotone, replay-safe)

__device__ __forceinline__ void grid_barrier() {
    __syncthreads();
    if (threadIdx.x == 0) {
        __threadfence();
        unsigned old = atomicAdd(&g_arrive, 1u);
        unsigned target = (old / NB + 1u) * NB;
        while ((int)(*(volatile unsigned*)&g_arrive - target) < 0)
            __nanosleep(32);
    }
    __syncthreads();
}

__global__ __launch_bounds__(NT, 4) void fused_kernel(const float* __restrict__ x,
                                                      const float* __restrict__ alpha,
                                                      float* __restrict__ out) {
    __shared__ float4 s_acc[8][DD / 4];   // 24 KB: per-warp column partials (phase 1)
    __shared__ float4 smean[DD / 4];      // 3 KB: sum_b row (phase 3)
    __shared__ float red[NT];             // phase 2 reduce
    __shared__ float s_coef;

    const int tid  = threadIdx.x;
    const int bid  = blockIdx.x;
    const int warp = tid >> 5;
    const int lane = tid & 31;

    // ---- Phase 1: column sums. One warp = exactly 8 rows; one block = 64 rows
    // (all in one batch: 512 blocks / 8 batches = 64 blocks per batch).
    // Perfectly balanced: no loops over chunks, no atomics.
    {
        const size_t rowbase = (size_t)bid * 64 + warp * RPW;
        const float4* xp = reinterpret_cast<const float4*>(x) + rowbase * (DD / 4) + lane;

        float4 acc[6];
#pragma unroll
        for (int i = 0; i < 6; i++) acc[i] = make_float4(0.f, 0.f, 0.f, 0.f);
#pragma unroll
        for (int r = 0; r < RPW; r++) {
#pragma unroll
            for (int i = 0; i < 6; i++) {
                float4 v = xp[(size_t)r * (DD / 4) + i * 32];
                acc[i].x += v.x; acc[i].y += v.y; acc[i].z += v.z; acc[i].w += v.w;
            }
        }
#pragma unroll
        for (int i = 0; i < 6; i++) s_acc[warp][lane + i * 32] = acc[i];
        __syncthreads();

        // 256 threads reduce 8 warp-partials x 768 cols (3 cols/thread)
#pragma unroll
        for (int k = 0; k < 3; k++) {
            const int col = tid + k * 256;
            const float* sa = reinterpret_cast<const float*>(s_acc);
            float s = 0.f;
#pragma unroll
            for (int w = 0; w < 8; w++) s += sa[w * DD + col];
            g_part[(size_t)bid * DD + col] = s;
        }
    }

    grid_barrier();

    // ---- Phase 2: 24 blocks (8 batches x 3 col-groups of 256). Reduce the 64
    // block-partials of each batch; also per-group sum of squares. ~2 us.
    if (bid < 24) {
        const int b = bid / 3;
        const int g = bid % 3;
        const int col = g * 256 + tid;

        const float* p = g_part + (size_t)b * 64 * DD + col;
        float a0 = 0.f, a1 = 0.f, a2 = 0.f, a3 = 0.f;
#pragma unroll
        for (int k = 0; k < 64; k += 4) {
            a0 += p[(size_t)(k + 0) * DD];
            a1 += p[(size_t)(k + 1) * DD];
            a2 += p[(size_t)(k + 2) * DD];
            a3 += p[(size_t)(k + 3) * DD];
        }
        const float s = (a0 + a1) + (a2 + a3);
        g_sum[b * DD + col] = s;

        red[tid] = s * s;
        __syncthreads();
        if (tid < 128) red[tid] += red[tid + 128];
        __syncthreads();
        if (tid < 64) red[tid] += red[tid + 64];
        __syncthreads();
        if (tid < 32) {
            float v = red[tid] + red[tid + 32];
#pragma unroll
            for (int off = 16; off > 0; off >>= 1)
                v += __shfl_xor_sync(0xFFFFFFFFu, v, off);
            if (tid == 0) g_sqpart[b * 3 + g] = v;
        }
    }

    grid_barrier();

    // ---- Phase 3: finalize, batches DESCENDING. At iteration j ALL 4096 warps
    // process exactly batch 7-j (row = ((7-j)<<12) | l, l = 4095 - wg fixed per
    // warp). Coherent 12MB descending frontier -> second x read mostly L2 hits
    // (R6/R9/R10 measured ~75-85 MB saved). Perfectly balanced: 8 rows/warp.
    {
        const int wg = bid * 8 + warp;          // 0..4095
        const int l  = 4095 - wg;
        const float a = alpha[l];
        const double denom = (double)DD * (double)DD
                           * (double)LL * (double)LL * (double)LL * (double)LL;

#pragma unroll 1
        for (int j = 0; j < 8; j++) {
            const int b = 7 - j;
            if (tid < DD / 4)
                smean[tid] = reinterpret_cast<const float4*>(g_sum)[b * (DD / 4) + tid];
            if (tid == 0) {
                const float sq = g_sqpart[b * 3 + 0] + g_sqpart[b * 3 + 1]
                               + g_sqpart[b * 3 + 2];
                s_coef = (float)((double)sq / denom);
            }
            __syncthreads();
            const float coef = s_coef;

            const int row = (b << 12) | l;
            const float4* xp = reinterpret_cast<const float4*>(x + (size_t)row * DD);
            float4 v[6];
            float dot = 0.f;
#pragma unroll
            for (int i = 0; i < 6; i++) {
                v[i] = xp[lane + i * 32];
                float4 m = smean[lane + i * 32];
                dot += v[i].x * m.x + v[i].y * m.y + v[i].z * m.z + v[i].w * m.w;
            }
#pragma unroll
            for (int off = 16; off > 0; off >>= 1)
                dot += __shfl_xor_sync(0xFFFFFFFFu, dot, off);

            const float y2 = dot * coef;

            float4* op = reinterpret_cast<float4*>(out + (size_t)row * DD);
#pragma unroll
            for (int i = 0; i < 6; i++) {
                float4 o;
                o.x = a + y2 * v[i].x;
                o.y = a + y2 * v[i].y;
                o.z = a + y2 * v[i].z;
                o.w = a + y2 * v[i].w;
                op[lane + i * 32] = o;
            }
            __syncthreads();   // smean reused next iteration
        }
    }
}

extern "C" void kernel_launch(void* const* d_in, const int* in_sizes, int n_in,
                              void* d_out, int out_size) {
    const float* x     = (const float*)d_in[0];   // [8, 4096, 768] f32
    const float* alpha = (const float*)d_in[1];   // [4096, 1] f32
    float* out = (float*)d_out;                   // [8, 4096, 768] f32

    fused_kernel<<<NB, NT>>>(x, alpha, out);
}